// round 5
// baseline (speedup 1.0000x reference)
#include <cuda_runtime.h>

#define KEY_DIM 128
#define NSEG 256

// Scratch: per-segment un-normalized weighted sums + denominators.
// Zero-initialized at module load; finalize_kernel resets them to zero after
// consuming, so every kernel_launch call (and every graph replay) starts from
// zeroed scratch without a dedicated zeroing kernel.
__device__ float g_num[NSEG * KEY_DIM];
__device__ float g_den[NSEG];

__device__ __forceinline__ void flush_seg(float4 acc, float den, int seg, int lane) {
    float* p = &g_num[seg * KEY_DIM + lane * 4];
    atomicAdd(p + 0, acc.x);
    atomicAdd(p + 1, acc.y);
    atomicAdd(p + 2, acc.z);
    atomicAdd(p + 3, acc.w);
    if (lane == 0) atomicAdd(&g_den[seg], den);
}

// One warp owns a contiguous, 4-aligned run of sorted nodes. Per batch of 4:
// issue 4 independent 512B row loads (MLP=4, streaming) + 1 int4 index load,
// then dot/exp/accumulate, and store 512B of zeros (streaming) to the matching
// output rows — fuses the 512MB output clear into the read pass.
__global__ void __launch_bounds__(256, 4) seg_attn_main(
    const float* __restrict__ feats,
    const float* __restrict__ Qm,
    const int*   __restrict__ bidx,
    float*       __restrict__ out,
    int V, int nodes_per_warp)
{
    int gw   = (blockIdx.x * blockDim.x + threadIdx.x) >> 5;
    int lane = threadIdx.x & 31;
    int start = gw * nodes_per_warp;          // multiple of 4
    if (start >= V) return;
    int end = min(V, start + nodes_per_warp);

    const float4* fq = reinterpret_cast<const float4*>(Qm);    // [256][32]
    const float4* ff = reinterpret_cast<const float4*>(feats); // [V][32]
    float4*       fo = reinterpret_cast<float4*>(out);         // [V][32]
    const float4  z4 = make_float4(0.f, 0.f, 0.f, 0.f);

    int cur = bidx[start];
    float4 q   = fq[cur * 32 + lane];
    float4 acc = make_float4(0.f, 0.f, 0.f, 0.f);
    float  den = 0.f;
    const float scale = 0.08838834764831845f;  // 1/sqrt(128)

    int i = start;
    for (; i + 4 <= end; i += 4) {
        int4   b4 = *reinterpret_cast<const int4*>(&bidx[i]);
        // Streaming loads: evict-first, don't churn L2 (pure single-use stream).
        float4 f0 = __ldcs(&ff[(i + 0) * 32 + lane]);
        float4 f1 = __ldcs(&ff[(i + 1) * 32 + lane]);
        float4 f2 = __ldcs(&ff[(i + 2) * 32 + lane]);
        float4 f3 = __ldcs(&ff[(i + 3) * 32 + lane]);

        // Streaming zero-stores for the fused output clear.
        __stcs(&fo[(i + 0) * 32 + lane], z4);
        __stcs(&fo[(i + 1) * 32 + lane], z4);
        __stcs(&fo[(i + 2) * 32 + lane], z4);
        __stcs(&fo[(i + 3) * 32 + lane], z4);

        int    bs[4] = {b4.x, b4.y, b4.z, b4.w};
        float4 fs[4] = {f0, f1, f2, f3};

        #pragma unroll
        for (int k = 0; k < 4; k++) {
            int    b = bs[k];
            float4 f = fs[k];
            if (b != cur) {
                flush_seg(acc, den, cur, lane);
                acc = make_float4(0.f, 0.f, 0.f, 0.f);
                den = 0.f;
                cur = b;
                q   = fq[cur * 32 + lane];
            }
            float p = f.x * q.x + f.y * q.y + f.z * q.z + f.w * q.w;
            p += __shfl_xor_sync(0xffffffffu, p, 16);
            p += __shfl_xor_sync(0xffffffffu, p, 8);
            p += __shfl_xor_sync(0xffffffffu, p, 4);
            p += __shfl_xor_sync(0xffffffffu, p, 2);
            p += __shfl_xor_sync(0xffffffffu, p, 1);

            float e = __expf(p * scale);
            acc.x += e * f.x;
            acc.y += e * f.y;
            acc.z += e * f.z;
            acc.w += e * f.w;
            den   += e;
        }
    }
    // Tail (< 4 nodes, or V not 4-aligned).
    for (; i < end; i++) {
        int    b = bidx[i];
        float4 f = __ldcs(&ff[i * 32 + lane]);
        __stcs(&fo[i * 32 + lane], z4);
        if (b != cur) {
            flush_seg(acc, den, cur, lane);
            acc = make_float4(0.f, 0.f, 0.f, 0.f);
            den = 0.f;
            cur = b;
            q   = fq[cur * 32 + lane];
        }
        float p = f.x * q.x + f.y * q.y + f.z * q.z + f.w * q.w;
        p += __shfl_xor_sync(0xffffffffu, p, 16);
        p += __shfl_xor_sync(0xffffffffu, p, 8);
        p += __shfl_xor_sync(0xffffffffu, p, 4);
        p += __shfl_xor_sync(0xffffffffu, p, 2);
        p += __shfl_xor_sync(0xffffffffu, p, 1);
        float e = __expf(p * scale);
        acc.x += e * f.x;
        acc.y += e * f.y;
        acc.z += e * f.z;
        acc.w += e * f.w;
        den   += e;
    }
    flush_seg(acc, den, cur, lane);
}

// Normalize + write the 256 live rows, then reset scratch to zero so the next
// call (graph replay) starts from a clean state.
__global__ void finalize_kernel(float* __restrict__ out) {
    int b = blockIdx.x;   // 0..255
    int d = threadIdx.x;  // 0..127
    float den = g_den[b];
    float num = g_num[b * KEY_DIM + d];
    __syncthreads();                 // all reads done before any reset
    float v = (den > 0.f) ? (num / den) : 0.f;
    out[b * KEY_DIM + d] = v;
    g_num[b * KEY_DIM + d] = 0.0f;   // reset scratch for next replay
    if (d == 0) g_den[b] = 0.0f;
}

extern "C" void kernel_launch(void* const* d_in, const int* in_sizes, int n_in,
                              void* d_out, int out_size) {
    const float* feats = (const float*)d_in[0];   // [V,128] fp32
    const float* Qm    = (const float*)d_in[1];   // [256,128] fp32
    const int*   bidx  = (const int*)d_in[2];     // [V] int32, sorted
    int V = in_sizes[2];
    float* out = (float*)d_out;                   // [V,128] fp32

    // 1) Fused: scores + exp + weighted accumulation + output zeroing
    //    (single pass: 512MB read + 512MB write, mixed DRAM traffic).
    const int blocks = 592;           // 4 blocks/SM x 148 SMs
    const int warps  = blocks * 8;    // 256 threads/block
    int npw = (V + warps - 1) / warps;
    npw = (npw + 3) & ~3;             // 4-aligned so int4 index loads are aligned
    seg_attn_main<<<blocks, 256>>>(feats, Qm, bidx, out, V, npw);

    // 2) Normalize, write the 256 live rows, reset scratch for next replay.
    finalize_kernel<<<NSEG, KEY_DIM>>>(out);
}